// round 1
// baseline (speedup 1.0000x reference)
#include <cuda_runtime.h>
#include <cuda_bf16.h>

#define EPSF 1e-6f
#define TWO_PI_F 6.283185307179586f

// Scratch (no device allocation allowed)
__device__ float g_ev[8192];     // per-event A_i * B_i
__device__ float g_base[2048];   // per-block base-rate partial sums

// ---------------------------------------------------------------------------
// Kernel 1: one block per event i.
//   - excitation sum over M past points (fused single-exp kernel)
//   - spatial grid factor A_i = sum_g exp(-|x_g - x_i|^2 / (2 sigma^2))
//   - temporal grid factor B_i = sum_{tau > t_i} exp(-omega (tau - t_i))
// Writes out[i] = log(mu_i + C * S_i + eps) and g_ev[i] = A_i * B_i.
// ---------------------------------------------------------------------------
__global__ __launch_bounds__(256) void k_events(
    const float* __restrict__ x, const float* __restrict__ t,
    const float* __restrict__ past_x, const float* __restrict__ past_t,
    const float* __restrict__ cov,
    const float* __restrict__ x_grid, const float* __restrict__ t_grid,
    const float* __restrict__ beta,
    const float* __restrict__ p_alpha, const float* __restrict__ p_sigma,
    const float* __restrict__ p_omega,
    int M, int G, int T, int D,
    float* __restrict__ out)
{
    __shared__ float smS[8], smA[8], smB[8];
    const int i   = blockIdx.x;
    const int tid = threadIdx.x;

    const float alpha = *p_alpha;
    const float sigma = *p_sigma;
    const float omega = *p_omega;
    const float inv2s2 = 1.0f / (2.0f * sigma * sigma);
    const float Cf     = alpha * omega / (TWO_PI_F * sigma * sigma);

    const float xi = x[2 * i];
    const float yi = x[2 * i + 1];
    const float ti = t[i];

    // ---- excitation over past points ----
    const float2* __restrict__ px = reinterpret_cast<const float2*>(past_x) + (size_t)i * M;
    const float*  __restrict__ pt = past_t + (size_t)i * M;

    float s = 0.0f;
    for (int j = tid; j < M; j += 256) {
        float2 p  = px[j];
        float  dt = ti - pt[j];
        float  dx = xi - p.x;
        float  dy = yi - p.y;
        float  r2 = dx * dx + dy * dy;
        if (dt > 0.0f)
            s += __expf(-(r2 * inv2s2 + omega * dt));   // fused spatial*temporal exp
    }

    // ---- spatial grid factor A_i ----
    float a = 0.0f;
    const float2* __restrict__ gx = reinterpret_cast<const float2*>(x_grid);
    for (int g = tid; g < G; g += 256) {
        float2 p  = gx[g];
        float  dx = p.x - xi;
        float  dy = p.y - yi;
        a += __expf(-(dx * dx + dy * dy) * inv2s2);
    }

    // ---- temporal grid factor B_i ----
    float b = 0.0f;
    for (int k = tid; k < T; k += 256) {
        float dtau = t_grid[k] - ti;
        if (dtau > 0.0f)
            b += __expf(-omega * dtau);
    }

    // ---- deterministic block reductions (warp shuffle + shared) ----
    #pragma unroll
    for (int o = 16; o > 0; o >>= 1) {
        s += __shfl_down_sync(0xffffffffu, s, o);
        a += __shfl_down_sync(0xffffffffu, a, o);
        b += __shfl_down_sync(0xffffffffu, b, o);
    }
    const int warp = tid >> 5;
    const int lane = tid & 31;
    if (lane == 0) { smS[warp] = s; smA[warp] = a; smB[warp] = b; }
    __syncthreads();

    if (tid == 0) {
        float S = 0.0f, A = 0.0f, B = 0.0f;
        #pragma unroll
        for (int w = 0; w < 8; w++) { S += smS[w]; A += smA[w]; B += smB[w]; }

        // baseline mu_i = max(cov_i . beta, eps)
        float mu = 0.0f;
        const float* __restrict__ ci = cov + (size_t)i * D;
        for (int d = 0; d < D; d++) mu = fmaf(ci[d], beta[d], mu);
        mu = fmaxf(mu, EPSF);

        float lam = mu + Cf * S;
        out[i]    = logf(lam + EPSF);
        g_ev[i]   = A * B;
    }
}

// ---------------------------------------------------------------------------
// Kernel 2: base-rate grid sum: sum_r max(z[r,:].beta, eps), block partials.
// rows = T*G, D assumed multiple of 4 (D=16 here).
// ---------------------------------------------------------------------------
__global__ __launch_bounds__(256) void k_base(
    const float* __restrict__ z, const float* __restrict__ beta,
    int rows, int D)
{
    __shared__ float sm[8];
    const int tid = threadIdx.x;

    float bta[16];
    #pragma unroll
    for (int d = 0; d < 16; d++) bta[d] = (d < D) ? beta[d] : 0.0f;

    float s = 0.0f;
    if ((D & 3) == 0 && D <= 16) {
        const int dq = D >> 2;
        for (int r = blockIdx.x * blockDim.x + tid; r < rows; r += gridDim.x * blockDim.x) {
            const float4* __restrict__ zr = reinterpret_cast<const float4*>(z + (size_t)r * D);
            float dot = 0.0f;
            #pragma unroll
            for (int q = 0; q < 4; q++) {
                if (q < dq) {
                    float4 v = zr[q];
                    dot = fmaf(v.x, bta[4 * q + 0], dot);
                    dot = fmaf(v.y, bta[4 * q + 1], dot);
                    dot = fmaf(v.z, bta[4 * q + 2], dot);
                    dot = fmaf(v.w, bta[4 * q + 3], dot);
                }
            }
            s += fmaxf(dot, EPSF);
        }
    } else {
        for (int r = blockIdx.x * blockDim.x + tid; r < rows; r += gridDim.x * blockDim.x) {
            float dot = 0.0f;
            for (int d = 0; d < D; d++) dot = fmaf(z[(size_t)r * D + d], beta[d], dot);
            s += fmaxf(dot, EPSF);
        }
    }

    #pragma unroll
    for (int o = 16; o > 0; o >>= 1)
        s += __shfl_down_sync(0xffffffffu, s, o);
    if ((tid & 31) == 0) sm[tid >> 5] = s;
    __syncthreads();
    if (tid == 0) {
        float S = 0.0f;
        #pragma unroll
        for (int w = 0; w < 8; w++) S += sm[w];
        g_base[blockIdx.x] = S;
    }
}

// ---------------------------------------------------------------------------
// Kernel 3: final deterministic reduce -> out[N] = integral
// ---------------------------------------------------------------------------
__global__ __launch_bounds__(256) void k_final(
    const float* __restrict__ t_grid,
    const float* __restrict__ p_alpha, const float* __restrict__ p_sigma,
    const float* __restrict__ p_omega,
    int N, int G, int nb,
    float* __restrict__ out)
{
    __shared__ float smE[8], smB[8];
    const int tid = threadIdx.x;

    float e = 0.0f;
    for (int i = tid; i < N; i += 256) e += g_ev[i];
    float b = 0.0f;
    for (int i = tid; i < nb; i += 256) b += g_base[i];

    #pragma unroll
    for (int o = 16; o > 0; o >>= 1) {
        e += __shfl_down_sync(0xffffffffu, e, o);
        b += __shfl_down_sync(0xffffffffu, b, o);
    }
    if ((tid & 31) == 0) { smE[tid >> 5] = e; smB[tid >> 5] = b; }
    __syncthreads();

    if (tid == 0) {
        float E = 0.0f, B = 0.0f;
        #pragma unroll
        for (int w = 0; w < 8; w++) { E += smE[w]; B += smB[w]; }

        const float alpha = *p_alpha;
        const float sigma = *p_sigma;
        const float omega = *p_omega;
        const float Cf = alpha * omega / (TWO_PI_F * sigma * sigma);
        const float dt_step = t_grid[1] - t_grid[0];
        const float dxdy = 1.0f / (float)G;

        out[N] = (B + Cf * E) * dxdy * dt_step;
    }
}

// ---------------------------------------------------------------------------
// Launch: inputs in metadata order:
// 0:x (N,2) 1:t (N) 2:past_x (N,M,2) 3:past_t (N,M) 4:covariates_xt (N,D)
// 5:z_grid (T,G,D) 6:x_grid (G,2) 7:t_grid (T) 8:beta (D)
// 9:alpha 10:sigma 11:omega
// ---------------------------------------------------------------------------
extern "C" void kernel_launch(void* const* d_in, const int* in_sizes, int n_in,
                              void* d_out, int out_size)
{
    const float* x       = (const float*)d_in[0];
    const float* t       = (const float*)d_in[1];
    const float* past_x  = (const float*)d_in[2];
    const float* past_t  = (const float*)d_in[3];
    const float* cov     = (const float*)d_in[4];
    const float* z_grid  = (const float*)d_in[5];
    const float* x_grid  = (const float*)d_in[6];
    const float* t_grid  = (const float*)d_in[7];
    const float* beta    = (const float*)d_in[8];
    const float* p_alpha = (const float*)d_in[9];
    const float* p_sigma = (const float*)d_in[10];
    const float* p_omega = (const float*)d_in[11];
    float* out = (float*)d_out;

    const int N = in_sizes[1];
    const int M = in_sizes[3] / N;
    const int D = in_sizes[8];
    const int G = in_sizes[6] / 2;
    const int T = in_sizes[7];
    const int rows = in_sizes[5] / D;   // T*G

    const int nb = 128;                 // base-kernel blocks (partials fit g_base)

    k_events<<<N, 256>>>(x, t, past_x, past_t, cov, x_grid, t_grid, beta,
                         p_alpha, p_sigma, p_omega, M, G, T, D, out);
    k_base<<<nb, 256>>>(z_grid, beta, rows, D);
    k_final<<<1, 256>>>(t_grid, p_alpha, p_sigma, p_omega, N, G, nb, out);
}